// round 14
// baseline (speedup 1.0000x reference)
#include <cuda_runtime.h>
#include <math.h>

#define NB    256
#define NT    256
#define NV    128
#define ND    384
#define NH    6
#define NL    6
#define NFF   1536
#define NTOK  (NB*NT)        /* 65536 */
#define NQKV  (3*ND)         /* 1152  */

typedef unsigned short u16;
typedef unsigned int   u32;

// ---------------- scratch (device globals; allocation-free) ----------------
__device__ float g_x    [NTOK*(size_t)ND];
__device__ u16   g_xn16 [NTOK*(size_t)ND];
__device__ u16   g_qkv16[NTOK*(size_t)NQKV];
__device__ u16   g_ff16 [NTOK*(size_t)NFF];
__device__ u16   g_wqkv16 [NL*(size_t)ND*NQKV];
__device__ u16   g_wproj16[NL*(size_t)ND*ND];
__device__ u16   g_w1_16  [NL*(size_t)ND*NFF];
__device__ u16   g_w2_16  [NL*(size_t)NFF*ND];
__device__ u16   g_wlm16  [(size_t)ND*NV];

// ---------------- fp16 helpers (no cuda_fp16.h) ----------------
__device__ __forceinline__ u16 f2h(float f){
    u16 h; asm("cvt.rn.f16.f32 %0, %1;" : "=h"(h) : "f"(f)); return h;
}
__device__ __forceinline__ u32 f2h2(float lo, float hi){
    u32 r; asm("cvt.rn.f16x2.f32 %0, %1, %2;" : "=r"(r) : "f"(hi), "f"(lo)); return r;
}

// ---------------- fused embedding + LayerNorm(layer0) ----------------
__global__ void __launch_bounds__(96)
k_embed_ln(const int* __restrict__ idx, const float* __restrict__ tok,
           const float* __restrict__ pos, const float* __restrict__ g,
           const float* __restrict__ bb, float* __restrict__ x,
           u16* __restrict__ y)
{
    int row = blockIdx.x;
    int t   = threadIdx.x;
    int v   = idx[row];
    float4 a = ((const float4*)(tok + (size_t)v*ND))[t];
    float4 p = ((const float4*)(pos + (size_t)(row & (NT-1))*ND))[t];
    float4 vv; vv.x=a.x+p.x; vv.y=a.y+p.y; vv.z=a.z+p.z; vv.w=a.w+p.w;
    ((float4*)(x + (size_t)row*ND))[t] = vv;

    float s  = vv.x+vv.y+vv.z+vv.w;
    float ss = vv.x*vv.x+vv.y*vv.y+vv.z*vv.z+vv.w*vv.w;
    #pragma unroll
    for (int o=16;o>0;o>>=1){
        s  += __shfl_xor_sync(0xffffffffu, s,  o);
        ss += __shfl_xor_sync(0xffffffffu, ss, o);
    }
    __shared__ float rs[3], rq[3];
    if ((t&31)==0){ rs[t>>5]=s; rq[t>>5]=ss; }
    __syncthreads();
    float tot  = rs[0]+rs[1]+rs[2];
    float totq = rq[0]+rq[1]+rq[2];
    float mean = tot * (1.f/ND);
    float var  = totq * (1.f/ND) - mean*mean;
    float rstd = rsqrtf(var + 1e-5f);
    float4 gg = ((const float4*)g)[t];
    float4 bv = ((const float4*)bb)[t];
    uint2 o2;
    o2.x = f2h2((vv.x-mean)*rstd*gg.x+bv.x, (vv.y-mean)*rstd*gg.y+bv.y);
    o2.y = f2h2((vv.z-mean)*rstd*gg.z+bv.z, (vv.w-mean)*rstd*gg.w+bv.w);
    *(uint2*)(y + (size_t)row*ND + t*4) = o2;
}

// ---------------- QKV weight repack to fp16 [d][j] -------------------------
__global__ void k_repack(const float* __restrict__ Wq, const float* __restrict__ Wk,
                         const float* __restrict__ Wv, u16* __restrict__ Wp)
{
    int i = blockIdx.x*blockDim.x + threadIdx.x;
    const int TOT = NL*ND*NQKV;
    if (i >= TOT) return;
    int j = i % NQKV;
    int d = (i / NQKV) % ND;
    int l = i / (NQKV*ND);
    const float* src; int c;
    if (j < ND)          { src = Wq; c = j;        }
    else if (j < 2*ND)   { src = Wk; c = j - ND;   }
    else                 { src = Wv; c = j - 2*ND; }
    int h = c >> 6, k = c & 63;
    Wp[i] = f2h(src[((size_t)((l*NH + h)*ND + d) << 6) + k]);
}

// ---------------- fp32 -> fp16 convert (paired) ----------------
__global__ void k_cvt(const float* __restrict__ s, u32* __restrict__ d, int n2)
{
    int i = blockIdx.x*blockDim.x + threadIdx.x;
    if (i < n2) d[i] = f2h2(s[2*i], s[2*i+1]);
}

// ---------------- LayerNorm (fp32 in, fp16 out), 96 thr / row --------------
__global__ void __launch_bounds__(96)
k_ln(const float* __restrict__ x, const float* __restrict__ g,
     const float* __restrict__ bb, u16* __restrict__ y)
{
    int row = blockIdx.x;
    int t   = threadIdx.x;
    float4 vv = ((const float4*)(x + (size_t)row*ND))[t];
    float s  = vv.x+vv.y+vv.z+vv.w;
    float ss = vv.x*vv.x+vv.y*vv.y+vv.z*vv.z+vv.w*vv.w;
    #pragma unroll
    for (int o=16;o>0;o>>=1){
        s  += __shfl_xor_sync(0xffffffffu, s,  o);
        ss += __shfl_xor_sync(0xffffffffu, ss, o);
    }
    __shared__ float rs[3], rq[3];
    if ((t&31)==0){ rs[t>>5]=s; rq[t>>5]=ss; }
    __syncthreads();
    float tot  = rs[0]+rs[1]+rs[2];
    float totq = rq[0]+rq[1]+rq[2];
    float mean = tot * (1.f/ND);
    float var  = totq * (1.f/ND) - mean*mean;
    float rstd = rsqrtf(var + 1e-5f);
    float4 gg = ((const float4*)g)[t];
    float4 bv = ((const float4*)bb)[t];
    uint2 o2;
    o2.x = f2h2((vv.x-mean)*rstd*gg.x+bv.x, (vv.y-mean)*rstd*gg.y+bv.y);
    o2.y = f2h2((vv.z-mean)*rstd*gg.z+bv.z, (vv.w-mean)*rstd*gg.w+bv.w);
    *(uint2*)(y + (size_t)row*ND + t*4) = o2;
}

// ================== mma / ldmatrix / cp.async primitives ==================
__device__ __forceinline__ void cp16(u32 dst, const void* src){
    asm volatile("cp.async.cg.shared.global [%0], [%1], 16;\n" :: "r"(dst), "l"(src));
}
__device__ __forceinline__ void ldm_x4(u32* r, u32 a){
    asm volatile("ldmatrix.sync.aligned.m8n8.x4.shared.b16 {%0,%1,%2,%3}, [%4];"
        : "=r"(r[0]),"=r"(r[1]),"=r"(r[2]),"=r"(r[3]) : "r"(a));
}
__device__ __forceinline__ void ldm_x4t(u32* r, u32 a){
    asm volatile("ldmatrix.sync.aligned.m8n8.x4.trans.shared.b16 {%0,%1,%2,%3}, [%4];"
        : "=r"(r[0]),"=r"(r[1]),"=r"(r[2]),"=r"(r[3]) : "r"(a));
}
__device__ __forceinline__ void mma_f16(float* c, const u32* a, const u32* b){
    asm volatile("mma.sync.aligned.m16n8k16.row.col.f32.f16.f16.f32 "
      "{%0,%1,%2,%3}, {%4,%5,%6,%7}, {%8,%9}, {%0,%1,%2,%3};\n"
      : "+f"(c[0]),"+f"(c[1]),"+f"(c[2]),"+f"(c[3])
      : "r"(a[0]),"r"(a[1]),"r"(a[2]),"r"(a[3]), "r"(b[0]),"r"(b[1]));
}

// ================== fp16 tensor-core GEMM (K-tile 64, 3-stage) =============
// C[M,N] = A[M,K] @ B[K,N]; A,B fp16 (u16); out fp32 or fp16;
// (+bias)(+res)(relu). Block 128x128x64, 8 warps (2x4), warp tile 64x32.
// 3-stage cp.async ring, 32KB/stage; wait_group 1 in steady state.
#define GSMEM (3*32768)

template<int OUTF32,int HAS_BIAS,int RES,int RELU>
__global__ void __launch_bounds__(256,2)
k_gemm_h(const u16* __restrict__ A, const u16* __restrict__ Bm,
         const float* __restrict__ bias, float* __restrict__ Cf,
         u16* __restrict__ Ch, int M, int N, int K)
{
    extern __shared__ __align__(16) u16 dsm[];
    const u32 sb = (u32)__cvta_generic_to_shared(dsm);

    const int tid  = threadIdx.x;
    const int warp = tid >> 5;
    const int lane = tid & 31;
    const int g    = lane >> 2;
    const int tig  = lane & 3;
    const int arow = lane & 15;
    const int asel = lane >> 4;
    const int wm   = (warp >> 2) * 64;
    const int wn   = (warp & 3) * 32;
    const int bm   = blockIdx.y * 128;
    const int bn   = blockIdx.x * 128;

    float acc[4][4][4];
    #pragma unroll
    for (int i=0;i<4;i++)
        #pragma unroll
        for (int j=0;j<4;j++)
            #pragma unroll
            for (int r=0;r<4;r++) acc[i][j][r]=0.f;

    // stage s at sb + s*32768: A 128 rows x 128B (8-chunk swz c^=r&7),
    //                          B @+16384, 64 rows x 256B (c^=k&7)
    auto issue = [&](int s, int k0){
        u32 sA = sb + (u32)s*32768u;
        u32 sB = sA + 16384u;
        #pragma unroll
        for (int it=0; it<4; it++){
            int ix = it*256 + tid;          // 0..1023
            int r = ix >> 3, c = ix & 7;
            cp16(sA + r*128 + ((c ^ (r&7)) << 4),
                 A + (size_t)(bm+r)*K + k0 + c*8);
        }
        #pragma unroll
        for (int it=0; it<4; it++){
            int ix = it*256 + tid;          // 0..1023
            int r = ix >> 4, c = ix & 15;
            cp16(sB + r*256 + ((c ^ (r&7)) << 4),
                 Bm + (size_t)(k0+r)*N + bn + c*8);
        }
        asm volatile("cp.async.commit_group;\n");
    };

    const int nk = K >> 6;
    issue(0, 0);
    if (nk > 1) issue(1, 64);
    int s = 0;

    for (int it = 0; it < nk; it++){
        if (it + 1 < nk) asm volatile("cp.async.wait_group 1;\n");
        else             asm volatile("cp.async.wait_group 0;\n");
        __syncthreads();
        if (it + 2 < nk){
            int s2 = s + 2; if (s2 >= 3) s2 -= 3;
            issue(s2, (it+2) << 6);
        }

        u32 sA = sb + (u32)s*32768u;
        u32 sB = sA + 16384u;
        #pragma unroll
        for (int ks=0; ks<4; ks++){
            u32 af[4][4], bf[4][2];
            #pragma unroll
            for (int mt=0; mt<4; mt++){
                int m = wm + mt*16 + arow;
                u32 ad = sA + (u32)(m*128 + ((((ks<<1)|asel) ^ (m&7)) << 4));
                ldm_x4(af[mt], ad);
            }
            #pragma unroll
            for (int p=0; p<2; p++){
                int kk = ks*16 + arow;
                int nb = (wn + p*16)*2 + asel*16;   // byte offset, 16-aligned
                u32 bd = sB + (u32)(kk*256 + (((nb>>4) ^ (kk & 7)) << 4));
                u32 r[4]; ldm_x4t(r, bd);
                bf[2*p][0]=r[0];   bf[2*p][1]=r[1];
                bf[2*p+1][0]=r[2]; bf[2*p+1][1]=r[3];
            }
            #pragma unroll
            for (int mt=0; mt<4; mt++)
                #pragma unroll
                for (int nt=0; nt<4; nt++)
                    mma_f16(acc[mt][nt], af[mt], bf[nt]);
        }
        if (++s == 3) s = 0;
    }

    #pragma unroll
    for (int mt=0; mt<4; mt++){
        #pragma unroll
        for (int nt=0; nt<4; nt++){
            int col = bn + wn + nt*8 + tig*2;
            float bx=0.f, by=0.f;
            if (HAS_BIAS){ float2 bb = *(const float2*)&bias[col]; bx=bb.x; by=bb.y; }
            #pragma unroll
            for (int hh=0; hh<2; hh++){
                int row = bm + wm + mt*16 + g + hh*8;
                size_t cix = (size_t)row * N + col;
                float vx = acc[mt][nt][hh*2+0] + bx;
                float vy = acc[mt][nt][hh*2+1] + by;
                if (RES){ float2 r = *(const float2*)&Cf[cix]; vx += r.x; vy += r.y; }
                if (RELU){ vx = fmaxf(vx,0.f); vy = fmaxf(vy,0.f); }
                if (OUTF32){
                    float2 o; o.x=vx; o.y=vy;
                    *(float2*)&Cf[cix] = o;
                } else {
                    *(u32*)(Ch + cix) = f2h2(vx, vy);
                }
            }
        }
    }
}

// ================== fp16 tensor-core causal flash attention ==================
__global__ void __launch_bounds__(128)
k_attn_h(const u16* __restrict__ qkv, u16* __restrict__ out)
{
    __shared__ __align__(16) u16 sQ[64*64];
    __shared__ __align__(16) u16 sK[2][64*64];
    __shared__ __align__(16) u16 sV[2][64*64];

    const int tid  = threadIdx.x;
    const int warp = tid >> 5;
    const int lane = tid & 31;
    const int g    = lane >> 2;
    const int tig  = lane & 3;
    const int arow = lane & 15;
    const int asel = lane >> 4;
    const int bh   = blockIdx.x;
    const int qt   = blockIdx.y;
    const int b    = bh / NH, h = bh % NH;
    const u16* base = qkv + (size_t)b * NT * NQKV + h * 64;

    u32 qa = (u32)__cvta_generic_to_shared(sQ);

    #pragma unroll
    for (int i=0;i<4;i++){
        int ix = tid + i*128;
        int r = ix >> 3, c = ix & 7;
        cp16(qa + r*128 + ((c ^ (r&7)) << 4),
             base + (size_t)(qt*64 + r)*NQKV + c*8);
    }
    auto issueKV = [&](int bufi, int kt){
        u32 ka = (u32)__cvta_generic_to_shared(&sK[bufi][0]);
        u32 va = (u32)__cvta_generic_to_shared(&sV[bufi][0]);
        #pragma unroll
        for (int i=0;i<4;i++){
            int ix = tid + i*128;
            int r = ix >> 3, c = ix & 7;
            u32 off = (u32)(r*128 + ((c ^ (r&7)) << 4));
            const u16* kb = base + ND + (size_t)(kt*64 + r)*NQKV + c*8;
            cp16(ka + off, kb);
            cp16(va + off, kb + ND);
        }
        asm volatile("cp.async.commit_group;\n");
    };
    issueKV(0, 0);

    float oc[8][4];
    #pragma unroll
    for (int j=0;j<8;j++)
        #pragma unroll
        for (int r=0;r<4;r++) oc[j][r]=0.f;
    float m0=-1e30f, m1=-1e30f, l0=0.f, l1=0.f;
    const float scale = 0.125f;
    int buf = 0;
    const int qrow = warp*16 + arow;
    const u32 qad0 = qa + (u32)(qrow*128);

    for (int kt = 0; kt <= qt; kt++){
        asm volatile("cp.async.wait_group 0;\n");
        __syncthreads();
        if (kt < qt) issueKV(buf ^ 1, kt + 1);

        u32 ka = (u32)__cvta_generic_to_shared(&sK[buf][0]);
        u32 va = (u32)__cvta_generic_to_shared(&sV[buf][0]);

        float sc[8][4];
        #pragma unroll
        for (int j=0;j<8;j++)
            #pragma unroll
            for (int r=0;r<4;r++) sc[j][r]=0.f;
        #pragma unroll
        for (int ks=0; ks<4; ks++){
            u32 af[4];
            ldm_x4(af, qad0 + (u32)((((ks<<1)|asel) ^ (qrow&7)) << 4));
            #pragma unroll
            for (int jp=0; jp<4; jp++){
                int rr = jp*16 + arow;
                u32 r[4];
                ldm_x4(r, ka + (u32)(rr*128 + ((((ks<<1)|asel) ^ (rr&7)) << 4)));
                u32 b0[2] = {r[0], r[2]};
                u32 b1[2] = {r[1], r[3]};
                mma_f16(sc[2*jp],   af, b0);
                mma_f16(sc[2*jp+1], af, b1);
            }
        }
        #pragma unroll
        for (int j=0;j<8;j++)
            #pragma unroll
            for (int r=0;r<4;r++) sc[j][r] *= scale;

        if (kt == qt){
            int r0 = warp*16 + g, r1 = r0 + 8;
            #pragma unroll
            for (int j=0;j<8;j++){
                int c0 = 8*j + 2*tig, c1 = c0 + 1;
                if (c0 > r0) sc[j][0] = -1e30f;
                if (c1 > r0) sc[j][1] = -1e30f;
                if (c0 > r1) sc[j][2] = -1e30f;
                if (c1 > r1) sc[j][3] = -1e30f;
            }
        }

        float mx0 = -1e30f, mx1 = -1e30f;
        #pragma unroll
        for (int j=0;j<8;j++){
            mx0 = fmaxf(mx0, fmaxf(sc[j][0], sc[j][1]));
            mx1 = fmaxf(mx1, fmaxf(sc[j][2], sc[j][3]));
        }
        #pragma unroll
        for (int o=1;o<4;o<<=1){
            mx0 = fmaxf(mx0, __shfl_xor_sync(0xffffffffu, mx0, o));
            mx1 = fmaxf(mx1, __shfl_xor_sync(0xffffffffu, mx1, o));
        }
        float mn0 = fmaxf(m0, mx0), mn1 = fmaxf(m1, mx1);
        float cr0 = __expf(m0 - mn0), cr1 = __expf(m1 - mn1);
        float sm0 = 0.f, sm1 = 0.f;
        #pragma unroll
        for (int j=0;j<8;j++){
            sc[j][0] = __expf(sc[j][0] - mn0);
            sc[j][1] = __expf(sc[j][1] - mn0);
            sc[j][2] = __expf(sc[j][2] - mn1);
            sc[j][3] = __expf(sc[j][3] - mn1);
            sm0 += sc[j][0] + sc[j][1];
            sm1 += sc[j][2] + sc[j][3];
        }
        #pragma unroll
        for (int o=1;o<4;o<<=1){
            sm0 += __shfl_xor_sync(0xffffffffu, sm0, o);
            sm1 += __shfl_xor_sync(0xffffffffu, sm1, o);
        }
        l0 = l0*cr0 + sm0;  m0 = mn0;
        l1 = l1*cr1 + sm1;  m1 = mn1;
        #pragma unroll
        for (int j=0;j<8;j++){
            oc[j][0] *= cr0; oc[j][1] *= cr0;
            oc[j][2] *= cr1; oc[j][3] *= cr1;
        }

        #pragma unroll
        for (int kc=0; kc<4; kc++){
            u32 pa[4];
            pa[0] = f2h2(sc[2*kc][0],   sc[2*kc][1]);
            pa[1] = f2h2(sc[2*kc][2],   sc[2*kc][3]);
            pa[2] = f2h2(sc[2*kc+1][0], sc[2*kc+1][1]);
            pa[3] = f2h2(sc[2*kc+1][2], sc[2*kc+1][3]);
            #pragma unroll
            for (int p=0; p<4; p++){
                int rr = kc*16 + arow;
                u32 r[4];
                ldm_x4t(r, va + (u32)(rr*128 + ((((p<<1)|asel) ^ (rr&7)) << 4)));
                u32 b0[2] = {r[0], r[1]};
                u32 b1[2] = {r[2], r[3]};
                mma_f16(oc[2*p],   pa, b0);
                mma_f16(oc[2*p+1], pa, b1);
            }
        }
        buf ^= 1;
    }

    float inv0 = 1.f / l0, inv1 = 1.f / l1;
    int row0 = qt*64 + warp*16 + g;
    size_t t0 = ((size_t)b*NT + row0) * ND + h*64;
    size_t t1 = t0 + (size_t)8*ND;
    #pragma unroll
    for (int j=0;j<8;j++){
        *(u32*)(out + t0 + 8*j + 2*tig) = f2h2(oc[j][0]*inv0, oc[j][1]*inv0);
        *(u32*)(out + t1 + 8*j + 2*tig) = f2h2(oc[j][2]*inv1, oc[j][3]*inv1);
    }
}

// ---------------- host launch ----------------
extern "C" void kernel_launch(void* const* d_in, const int* in_sizes, int n_in,
                              void* d_out, int out_size)
{
    (void)in_sizes; (void)n_in; (void)out_size;
    const int*   idx   = (const int*)  d_in[0];
    const float* tok   = (const float*)d_in[1];
    const float* pos   = (const float*)d_in[2];
    const float* Wq    = (const float*)d_in[3];
    const float* Wk    = (const float*)d_in[4];
    const float* Wv    = (const float*)d_in[5];
    const float* Wproj = (const float*)d_in[6];
    const float* bproj = (const float*)d_in[7];
    const float* ln1g  = (const float*)d_in[8];
    const float* ln1b  = (const float*)d_in[9];
    const float* ln2g  = (const float*)d_in[10];
    const float* ln2b  = (const float*)d_in[11];
    const float* W1    = (const float*)d_in[12];
    const float* b1    = (const float*)d_in[13];
    const float* W2    = (const float*)d_in[14];
    const float* b2    = (const float*)d_in[15];
    const float* lnfg  = (const float*)d_in[16];
    const float* lnfb  = (const float*)d_in[17];
    const float* Wlm   = (const float*)d_in[18];
    const float* blm   = (const float*)d_in[19];
    float* out = (float*)d_out;

    float *x;
    u16 *xn16, *qkv16, *ff16, *wqkv16, *wproj16, *w1_16, *w2_16, *wlm16;
    cudaGetSymbolAddress((void**)&x,      g_x);
    cudaGetSymbolAddress((void**)&xn16,   g_xn16);
    cudaGetSymbolAddress((void**)&qkv16,  g_qkv16);
    cudaGetSymbolAddress((void**)&ff16,   g_ff16);
    cudaGetSymbolAddress((void**)&wqkv16, g_wqkv16);
    cudaGetSymbolAddress((void**)&wproj16,g_wproj16);
    cudaGetSymbolAddress((void**)&w1_16,  g_w1_16);
    cudaGetSymbolAddress((void**)&w2_16,  g_w2_16);
    cudaGetSymbolAddress((void**)&wlm16,  g_wlm16);

    cudaFuncSetAttribute(k_gemm_h<0,0,0,0>, cudaFuncAttributeMaxDynamicSharedMemorySize, GSMEM);
    cudaFuncSetAttribute(k_gemm_h<1,1,1,0>, cudaFuncAttributeMaxDynamicSharedMemorySize, GSMEM);
    cudaFuncSetAttribute(k_gemm_h<0,1,0,1>, cudaFuncAttributeMaxDynamicSharedMemorySize, GSMEM);
    cudaFuncSetAttribute(k_gemm_h<1,1,0,0>, cudaFuncAttributeMaxDynamicSharedMemorySize, GSMEM);

    k_embed_ln<<<NTOK,96>>>(idx, tok, pos, ln1g, ln1b, x, xn16);
    k_repack<<<(NL*ND*NQKV + 255)/256, 256>>>(Wq, Wk, Wv, wqkv16);
    k_cvt<<<(NL*ND*ND/2   + 255)/256, 256>>>(Wproj, (u32*)wproj16, NL*ND*ND/2);
    k_cvt<<<(NL*ND*NFF/2  + 255)/256, 256>>>(W1,    (u32*)w1_16,   NL*ND*NFF/2);
    k_cvt<<<(NL*NFF*ND/2  + 255)/256, 256>>>(W2,    (u32*)w2_16,   NL*NFF*ND/2);
    k_cvt<<<(ND*NV/2      + 255)/256, 256>>>(Wlm,   (u32*)wlm16,   ND*NV/2);

    for (int l = 0; l < NL; l++){
        if (l > 0)
            k_ln<<<NTOK,96>>>(x, ln1g + l*ND, ln1b + l*ND, xn16);
        k_gemm_h<0,0,0,0><<<dim3(NQKV/128, NTOK/128),256,GSMEM>>>(
            xn16, wqkv16 + (size_t)l*ND*NQKV, (const float*)0, (float*)0, qkv16,
            NTOK, NQKV, ND);
        k_attn_h<<<dim3(NB*NH, 4),128>>>(qkv16, xn16);
        k_gemm_h<1,1,1,0><<<dim3(ND/128, NTOK/128),256,GSMEM>>>(
            xn16, wproj16 + (size_t)l*ND*ND, bproj + l*ND, x, (u16*)0,
            NTOK, ND, ND);
        k_ln<<<NTOK,96>>>(x, ln2g + l*ND, ln2b + l*ND, xn16);
        k_gemm_h<0,1,0,1><<<dim3(NFF/128, NTOK/128),256,GSMEM>>>(
            xn16, w1_16 + (size_t)l*ND*NFF, b1 + l*NFF, (float*)0, ff16,
            NTOK, NFF, ND);
        k_gemm_h<1,1,1,0><<<dim3(ND/128, NTOK/128),256,GSMEM>>>(
            ff16, w2_16 + (size_t)l*NFF*ND, b2 + l*ND, x, (u16*)0,
            NTOK, ND, NFF);
    }
    k_ln<<<NTOK,96>>>(x, lnfg, lnfb, xn16);
    k_gemm_h<1,1,0,0><<<dim3(NV/128, NTOK/128),256,GSMEM>>>(
        xn16, wlm16, blm, out, (u16*)0, NTOK, NV, ND);
}

// round 15
// speedup vs baseline: 1.0124x; 1.0124x over previous
#include <cuda_runtime.h>
#include <math.h>

#define NB    256
#define NT    256
#define NV    128
#define ND    384
#define NH    6
#define NL    6
#define NFF   1536
#define NTOK  (NB*NT)        /* 65536 */
#define NQKV  (3*ND)         /* 1152  */

typedef unsigned short u16;
typedef unsigned int   u32;

// ---------------- scratch (device globals; allocation-free) ----------------
__device__ float g_x    [NTOK*(size_t)ND];
__device__ u16   g_xn16 [NTOK*(size_t)ND];
__device__ u16   g_qkv16[NTOK*(size_t)NQKV];
__device__ u16   g_ff16 [NTOK*(size_t)NFF];
__device__ u16   g_wqkv16 [NL*(size_t)ND*NQKV];
__device__ u16   g_wproj16[NL*(size_t)ND*ND];
__device__ u16   g_w1_16  [NL*(size_t)ND*NFF];
__device__ u16   g_w2_16  [NL*(size_t)NFF*ND];
__device__ u16   g_wlm16  [(size_t)ND*NV];

// ---------------- fp16 helpers (no cuda_fp16.h) ----------------
__device__ __forceinline__ u16 f2h(float f){
    u16 h; asm("cvt.rn.f16.f32 %0, %1;" : "=h"(h) : "f"(f)); return h;
}
__device__ __forceinline__ u32 f2h2(float lo, float hi){
    u32 r; asm("cvt.rn.f16x2.f32 %0, %1, %2;" : "=r"(r) : "f"(hi), "f"(lo)); return r;
}

// ---------------- fused embedding + LayerNorm(layer0) ----------------
__global__ void __launch_bounds__(96)
k_embed_ln(const int* __restrict__ idx, const float* __restrict__ tok,
           const float* __restrict__ pos, const float* __restrict__ g,
           const float* __restrict__ bb, float* __restrict__ x,
           u16* __restrict__ y)
{
    int row = blockIdx.x;
    int t   = threadIdx.x;
    int v   = idx[row];
    float4 a = ((const float4*)(tok + (size_t)v*ND))[t];
    float4 p = ((const float4*)(pos + (size_t)(row & (NT-1))*ND))[t];
    float4 vv; vv.x=a.x+p.x; vv.y=a.y+p.y; vv.z=a.z+p.z; vv.w=a.w+p.w;
    ((float4*)(x + (size_t)row*ND))[t] = vv;

    float s  = vv.x+vv.y+vv.z+vv.w;
    float ss = vv.x*vv.x+vv.y*vv.y+vv.z*vv.z+vv.w*vv.w;
    #pragma unroll
    for (int o=16;o>0;o>>=1){
        s  += __shfl_xor_sync(0xffffffffu, s,  o);
        ss += __shfl_xor_sync(0xffffffffu, ss, o);
    }
    __shared__ float rs[3], rq[3];
    if ((t&31)==0){ rs[t>>5]=s; rq[t>>5]=ss; }
    __syncthreads();
    float tot  = rs[0]+rs[1]+rs[2];
    float totq = rq[0]+rq[1]+rq[2];
    float mean = tot * (1.f/ND);
    float var  = totq * (1.f/ND) - mean*mean;
    float rstd = rsqrtf(var + 1e-5f);
    float4 gg = ((const float4*)g)[t];
    float4 bv = ((const float4*)bb)[t];
    uint2 o2;
    o2.x = f2h2((vv.x-mean)*rstd*gg.x+bv.x, (vv.y-mean)*rstd*gg.y+bv.y);
    o2.y = f2h2((vv.z-mean)*rstd*gg.z+bv.z, (vv.w-mean)*rstd*gg.w+bv.w);
    *(uint2*)(y + (size_t)row*ND + t*4) = o2;
}

// ---------------- QKV weight repack to fp16 [d][j] -------------------------
__global__ void k_repack(const float* __restrict__ Wq, const float* __restrict__ Wk,
                         const float* __restrict__ Wv, u16* __restrict__ Wp)
{
    int i = blockIdx.x*blockDim.x + threadIdx.x;
    const int TOT = NL*ND*NQKV;
    if (i >= TOT) return;
    int j = i % NQKV;
    int d = (i / NQKV) % ND;
    int l = i / (NQKV*ND);
    const float* src; int c;
    if (j < ND)          { src = Wq; c = j;        }
    else if (j < 2*ND)   { src = Wk; c = j - ND;   }
    else                 { src = Wv; c = j - 2*ND; }
    int h = c >> 6, k = c & 63;
    Wp[i] = f2h(src[((size_t)((l*NH + h)*ND + d) << 6) + k]);
}

// -------- merged fp32->fp16 conversion of all remaining weights ------------
__global__ void k_cvtall(const float* __restrict__ Wproj, const float* __restrict__ W1,
                         const float* __restrict__ W2, const float* __restrict__ Wlm,
                         u32* __restrict__ dproj, u32* __restrict__ d1,
                         u32* __restrict__ d2, u32* __restrict__ dlm)
{
    int i = blockIdx.x*blockDim.x + threadIdx.x;
    const int n0 = NL*ND*ND/2, n1 = NL*ND*NFF/2, n2 = NL*NFF*ND/2, n3 = ND*NV/2;
    if (i < n0){ dproj[i] = f2h2(Wproj[2*i], Wproj[2*i+1]); return; }
    i -= n0;
    if (i < n1){ d1[i] = f2h2(W1[2*i], W1[2*i+1]); return; }
    i -= n1;
    if (i < n2){ d2[i] = f2h2(W2[2*i], W2[2*i+1]); return; }
    i -= n2;
    if (i < n3){ dlm[i] = f2h2(Wlm[2*i], Wlm[2*i+1]); }
}
#define CVT_TOT (NL*ND*ND/2 + NL*ND*NFF/2 + NL*NFF*ND/2 + ND*NV/2)

// ---------------- LayerNorm (fp32 in, fp16 out), 96 thr / row --------------
__global__ void __launch_bounds__(96)
k_ln(const float* __restrict__ x, const float* __restrict__ g,
     const float* __restrict__ bb, u16* __restrict__ y)
{
    int row = blockIdx.x;
    int t   = threadIdx.x;
    float4 vv = ((const float4*)(x + (size_t)row*ND))[t];
    float s  = vv.x+vv.y+vv.z+vv.w;
    float ss = vv.x*vv.x+vv.y*vv.y+vv.z*vv.z+vv.w*vv.w;
    #pragma unroll
    for (int o=16;o>0;o>>=1){
        s  += __shfl_xor_sync(0xffffffffu, s,  o);
        ss += __shfl_xor_sync(0xffffffffu, ss, o);
    }
    __shared__ float rs[3], rq[3];
    if ((t&31)==0){ rs[t>>5]=s; rq[t>>5]=ss; }
    __syncthreads();
    float tot  = rs[0]+rs[1]+rs[2];
    float totq = rq[0]+rq[1]+rq[2];
    float mean = tot * (1.f/ND);
    float var  = totq * (1.f/ND) - mean*mean;
    float rstd = rsqrtf(var + 1e-5f);
    float4 gg = ((const float4*)g)[t];
    float4 bv = ((const float4*)bb)[t];
    uint2 o2;
    o2.x = f2h2((vv.x-mean)*rstd*gg.x+bv.x, (vv.y-mean)*rstd*gg.y+bv.y);
    o2.y = f2h2((vv.z-mean)*rstd*gg.z+bv.z, (vv.w-mean)*rstd*gg.w+bv.w);
    *(uint2*)(y + (size_t)row*ND + t*4) = o2;
}

// ================== mma / ldmatrix / cp.async primitives ==================
__device__ __forceinline__ void cp16(u32 dst, const void* src){
    asm volatile("cp.async.cg.shared.global [%0], [%1], 16;\n" :: "r"(dst), "l"(src));
}
__device__ __forceinline__ void ldm_x4(u32* r, u32 a){
    asm volatile("ldmatrix.sync.aligned.m8n8.x4.shared.b16 {%0,%1,%2,%3}, [%4];"
        : "=r"(r[0]),"=r"(r[1]),"=r"(r[2]),"=r"(r[3]) : "r"(a));
}
__device__ __forceinline__ void ldm_x4t(u32* r, u32 a){
    asm volatile("ldmatrix.sync.aligned.m8n8.x4.trans.shared.b16 {%0,%1,%2,%3}, [%4];"
        : "=r"(r[0]),"=r"(r[1]),"=r"(r[2]),"=r"(r[3]) : "r"(a));
}
__device__ __forceinline__ void mma_f16(float* c, const u32* a, const u32* b){
    asm volatile("mma.sync.aligned.m16n8k16.row.col.f32.f16.f16.f32 "
      "{%0,%1,%2,%3}, {%4,%5,%6,%7}, {%8,%9}, {%0,%1,%2,%3};\n"
      : "+f"(c[0]),"+f"(c[1]),"+f"(c[2]),"+f"(c[3])
      : "r"(a[0]),"r"(a[1]),"r"(a[2]),"r"(a[3]), "r"(b[0]),"r"(b[1]));
}

// ================== fp16 tensor-core GEMM (K-tile 64, 2-stage) =============
// C[M,N] = A[M,K] @ B[K,N]; A,B fp16 (u16); out fp32 or fp16;
// (+bias)(+res)(relu). Block 128x128x64, 8 warps (2x4), warp tile 64x32.
// 2-stage cp.async ring, 32KB/stage (A 16KB @128B rows + B 16KB @256B rows).
#define GSMEM (2*32768)

template<int OUTF32,int HAS_BIAS,int RES,int RELU>
__global__ void __launch_bounds__(256,2)
k_gemm_h(const u16* __restrict__ A, const u16* __restrict__ Bm,
         const float* __restrict__ bias, float* __restrict__ Cf,
         u16* __restrict__ Ch, int M, int N, int K)
{
    extern __shared__ __align__(16) u16 dsm[];
    const u32 sb = (u32)__cvta_generic_to_shared(dsm);

    const int tid  = threadIdx.x;
    const int warp = tid >> 5;
    const int lane = tid & 31;
    const int g    = lane >> 2;
    const int tig  = lane & 3;
    const int arow = lane & 15;
    const int asel = lane >> 4;
    const int wm   = (warp >> 2) * 64;
    const int wn   = (warp & 3) * 32;
    const int bm   = blockIdx.y * 128;
    const int bn   = blockIdx.x * 128;

    float acc[4][4][4];
    #pragma unroll
    for (int i=0;i<4;i++)
        #pragma unroll
        for (int j=0;j<4;j++)
            #pragma unroll
            for (int r=0;r<4;r++) acc[i][j][r]=0.f;

    // stage s at sb + s*32768: A 128 rows x 128B (8-chunk swz c^=r&7),
    //                          B @+16384, 64 rows x 256B (c^=k&7)
    auto issue = [&](int s, int k0){
        u32 sA = sb + (u32)s*32768u;
        u32 sB = sA + 16384u;
        #pragma unroll
        for (int it=0; it<4; it++){
            int ix = it*256 + tid;          // 0..1023
            int r = ix >> 3, c = ix & 7;
            cp16(sA + r*128 + ((c ^ (r&7)) << 4),
                 A + (size_t)(bm+r)*K + k0 + c*8);
        }
        #pragma unroll
        for (int it=0; it<4; it++){
            int ix = it*256 + tid;          // 0..1023
            int r = ix >> 4, c = ix & 15;
            cp16(sB + r*256 + ((c ^ (r&7)) << 4),
                 Bm + (size_t)(k0+r)*N + bn + c*8);
        }
        asm volatile("cp.async.commit_group;\n");
    };

    const int nk = K >> 6;
    issue(0, 0);
    int buf = 0;

    for (int it = 0; it < nk; it++){
        asm volatile("cp.async.wait_group 0;\n");
        __syncthreads();
        if (it + 1 < nk) issue(buf ^ 1, (it+1) << 6);

        u32 sA = sb + (u32)buf*32768u;
        u32 sB = sA + 16384u;
        #pragma unroll
        for (int ks=0; ks<4; ks++){
            u32 af[4][4], bf[4][2];
            #pragma unroll
            for (int mt=0; mt<4; mt++){
                int m = wm + mt*16 + arow;
                u32 ad = sA + (u32)(m*128 + ((((ks<<1)|asel) ^ (m&7)) << 4));
                ldm_x4(af[mt], ad);
            }
            #pragma unroll
            for (int p=0; p<2; p++){
                int kk = ks*16 + arow;
                int nb = (wn + p*16)*2 + asel*16;   // byte offset, 16-aligned
                u32 bd = sB + (u32)(kk*256 + (((nb>>4) ^ (kk & 7)) << 4));
                u32 r[4]; ldm_x4t(r, bd);
                bf[2*p][0]=r[0];   bf[2*p][1]=r[1];
                bf[2*p+1][0]=r[2]; bf[2*p+1][1]=r[3];
            }
            #pragma unroll
            for (int mt=0; mt<4; mt++)
                #pragma unroll
                for (int nt=0; nt<4; nt++)
                    mma_f16(acc[mt][nt], af[mt], bf[nt]);
        }
        buf ^= 1;
    }

    #pragma unroll
    for (int mt=0; mt<4; mt++){
        #pragma unroll
        for (int nt=0; nt<4; nt++){
            int col = bn + wn + nt*8 + tig*2;
            float bx=0.f, by=0.f;
            if (HAS_BIAS){ float2 bb = *(const float2*)&bias[col]; bx=bb.x; by=bb.y; }
            #pragma unroll
            for (int hh=0; hh<2; hh++){
                int row = bm + wm + mt*16 + g + hh*8;
                size_t cix = (size_t)row * N + col;
                float vx = acc[mt][nt][hh*2+0] + bx;
                float vy = acc[mt][nt][hh*2+1] + by;
                if (RES){ float2 r = *(const float2*)&Cf[cix]; vx += r.x; vy += r.y; }
                if (RELU){ vx = fmaxf(vx,0.f); vy = fmaxf(vy,0.f); }
                if (OUTF32){
                    float2 o; o.x=vx; o.y=vy;
                    *(float2*)&Cf[cix] = o;
                } else {
                    *(u32*)(Ch + cix) = f2h2(vx, vy);
                }
            }
        }
    }
}

// ================== fp16 tensor-core causal flash attention ==================
__global__ void __launch_bounds__(128)
k_attn_h(const u16* __restrict__ qkv, u16* __restrict__ out)
{
    __shared__ __align__(16) u16 sQ[64*64];
    __shared__ __align__(16) u16 sK[2][64*64];
    __shared__ __align__(16) u16 sV[2][64*64];

    const int tid  = threadIdx.x;
    const int warp = tid >> 5;
    const int lane = tid & 31;
    const int g    = lane >> 2;
    const int tig  = lane & 3;
    const int arow = lane & 15;
    const int asel = lane >> 4;
    const int bh   = blockIdx.x;
    const int qt   = blockIdx.y;
    const int b    = bh / NH, h = bh % NH;
    const u16* base = qkv + (size_t)b * NT * NQKV + h * 64;

    u32 qa = (u32)__cvta_generic_to_shared(sQ);

    #pragma unroll
    for (int i=0;i<4;i++){
        int ix = tid + i*128;
        int r = ix >> 3, c = ix & 7;
        cp16(qa + r*128 + ((c ^ (r&7)) << 4),
             base + (size_t)(qt*64 + r)*NQKV + c*8);
    }
    auto issueKV = [&](int bufi, int kt){
        u32 ka = (u32)__cvta_generic_to_shared(&sK[bufi][0]);
        u32 va = (u32)__cvta_generic_to_shared(&sV[bufi][0]);
        #pragma unroll
        for (int i=0;i<4;i++){
            int ix = tid + i*128;
            int r = ix >> 3, c = ix & 7;
            u32 off = (u32)(r*128 + ((c ^ (r&7)) << 4));
            const u16* kb = base + ND + (size_t)(kt*64 + r)*NQKV + c*8;
            cp16(ka + off, kb);
            cp16(va + off, kb + ND);
        }
        asm volatile("cp.async.commit_group;\n");
    };
    issueKV(0, 0);

    float oc[8][4];
    #pragma unroll
    for (int j=0;j<8;j++)
        #pragma unroll
        for (int r=0;r<4;r++) oc[j][r]=0.f;
    float m0=-1e30f, m1=-1e30f, l0=0.f, l1=0.f;
    const float scale = 0.125f;
    int buf = 0;
    const int qrow = warp*16 + arow;
    const u32 qad0 = qa + (u32)(qrow*128);

    for (int kt = 0; kt <= qt; kt++){
        asm volatile("cp.async.wait_group 0;\n");
        __syncthreads();
        if (kt < qt) issueKV(buf ^ 1, kt + 1);

        u32 ka = (u32)__cvta_generic_to_shared(&sK[buf][0]);
        u32 va = (u32)__cvta_generic_to_shared(&sV[buf][0]);

        float sc[8][4];
        #pragma unroll
        for (int j=0;j<8;j++)
            #pragma unroll
            for (int r=0;r<4;r++) sc[j][r]=0.f;
        #pragma unroll
        for (int ks=0; ks<4; ks++){
            u32 af[4];
            ldm_x4(af, qad0 + (u32)((((ks<<1)|asel) ^ (qrow&7)) << 4));
            #pragma unroll
            for (int jp=0; jp<4; jp++){
                int rr = jp*16 + arow;
                u32 r[4];
                ldm_x4(r, ka + (u32)(rr*128 + ((((ks<<1)|asel) ^ (rr&7)) << 4)));
                u32 b0[2] = {r[0], r[2]};
                u32 b1[2] = {r[1], r[3]};
                mma_f16(sc[2*jp],   af, b0);
                mma_f16(sc[2*jp+1], af, b1);
            }
        }
        #pragma unroll
        for (int j=0;j<8;j++)
            #pragma unroll
            for (int r=0;r<4;r++) sc[j][r] *= scale;

        if (kt == qt){
            int r0 = warp*16 + g, r1 = r0 + 8;
            #pragma unroll
            for (int j=0;j<8;j++){
                int c0 = 8*j + 2*tig, c1 = c0 + 1;
                if (c0 > r0) sc[j][0] = -1e30f;
                if (c1 > r0) sc[j][1] = -1e30f;
                if (c0 > r1) sc[j][2] = -1e30f;
                if (c1 > r1) sc[j][3] = -1e30f;
            }
        }

        float mx0 = -1e30f, mx1 = -1e30f;
        #pragma unroll
        for (int j=0;j<8;j++){
            mx0 = fmaxf(mx0, fmaxf(sc[j][0], sc[j][1]));
            mx1 = fmaxf(mx1, fmaxf(sc[j][2], sc[j][3]));
        }
        #pragma unroll
        for (int o=1;o<4;o<<=1){
            mx0 = fmaxf(mx0, __shfl_xor_sync(0xffffffffu, mx0, o));
            mx1 = fmaxf(mx1, __shfl_xor_sync(0xffffffffu, mx1, o));
        }
        float mn0 = fmaxf(m0, mx0), mn1 = fmaxf(m1, mx1);
        float cr0 = __expf(m0 - mn0), cr1 = __expf(m1 - mn1);
        float sm0 = 0.f, sm1 = 0.f;
        #pragma unroll
        for (int j=0;j<8;j++){
            sc[j][0] = __expf(sc[j][0] - mn0);
            sc[j][1] = __expf(sc[j][1] - mn0);
            sc[j][2] = __expf(sc[j][2] - mn1);
            sc[j][3] = __expf(sc[j][3] - mn1);
            sm0 += sc[j][0] + sc[j][1];
            sm1 += sc[j][2] + sc[j][3];
        }
        #pragma unroll
        for (int o=1;o<4;o<<=1){
            sm0 += __shfl_xor_sync(0xffffffffu, sm0, o);
            sm1 += __shfl_xor_sync(0xffffffffu, sm1, o);
        }
        l0 = l0*cr0 + sm0;  m0 = mn0;
        l1 = l1*cr1 + sm1;  m1 = mn1;
        #pragma unroll
        for (int j=0;j<8;j++){
            oc[j][0] *= cr0; oc[j][1] *= cr0;
            oc[j][2] *= cr1; oc[j][3] *= cr1;
        }

        #pragma unroll
        for (int kc=0; kc<4; kc++){
            u32 pa[4];
            pa[0] = f2h2(sc[2*kc][0],   sc[2*kc][1]);
            pa[1] = f2h2(sc[2*kc][2],   sc[2*kc][3]);
            pa[2] = f2h2(sc[2*kc+1][0], sc[2*kc+1][1]);
            pa[3] = f2h2(sc[2*kc+1][2], sc[2*kc+1][3]);
            #pragma unroll
            for (int p=0; p<4; p++){
                int rr = kc*16 + arow;
                u32 r[4];
                ldm_x4t(r, va + (u32)(rr*128 + ((((p<<1)|asel) ^ (rr&7)) << 4)));
                u32 b0[2] = {r[0], r[1]};
                u32 b1[2] = {r[2], r[3]};
                mma_f16(oc[2*p],   pa, b0);
                mma_f16(oc[2*p+1], pa, b1);
            }
        }
        buf ^= 1;
    }

    float inv0 = 1.f / l0, inv1 = 1.f / l1;
    int row0 = qt*64 + warp*16 + g;
    size_t t0 = ((size_t)b*NT + row0) * ND + h*64;
    size_t t1 = t0 + (size_t)8*ND;
    #pragma unroll
    for (int j=0;j<8;j++){
        *(u32*)(out + t0 + 8*j + 2*tig) = f2h2(oc[j][0]*inv0, oc[j][1]*inv0);
        *(u32*)(out + t1 + 8*j + 2*tig) = f2h2(oc[j][2]*inv1, oc[j][3]*inv1);
    }
}

// ---------------- host launch ----------------
extern "C" void kernel_launch(void* const* d_in, const int* in_sizes, int n_in,
                              void* d_out, int out_size)
{
    (void)in_sizes; (void)n_in; (void)out_size;
    const int*   idx   = (const int*)  d_in[0];
    const float* tok   = (const float*)d_in[1];
    const float* pos   = (const float*)d_in[2];
    const float* Wq    = (const float*)d_in[3];
    const float* Wk    = (const float*)d_in[4];
    const float* Wv    = (const float*)d_in[5];
    const float* Wproj = (const float*)d_in[6];
    const float* bproj = (const float*)d_in[7];
    const float* ln1g  = (const float*)d_in[8];
    const float* ln1b  = (const float*)d_in[9];
    const float* ln2g  = (const float*)d_in[10];
    const float* ln2b  = (const float*)d_in[11];
    const float* W1    = (const float*)d_in[12];
    const float* b1    = (const float*)d_in[13];
    const float* W2    = (const float*)d_in[14];
    const float* b2    = (const float*)d_in[15];
    const float* lnfg  = (const float*)d_in[16];
    const float* lnfb  = (const float*)d_in[17];
    const float* Wlm   = (const float*)d_in[18];
    const float* blm   = (const float*)d_in[19];
    float* out = (float*)d_out;

    float *x;
    u16 *xn16, *qkv16, *ff16, *wqkv16, *wproj16, *w1_16, *w2_16, *wlm16;
    cudaGetSymbolAddress((void**)&x,      g_x);
    cudaGetSymbolAddress((void**)&xn16,   g_xn16);
    cudaGetSymbolAddress((void**)&qkv16,  g_qkv16);
    cudaGetSymbolAddress((void**)&ff16,   g_ff16);
    cudaGetSymbolAddress((void**)&wqkv16, g_wqkv16);
    cudaGetSymbolAddress((void**)&wproj16,g_wproj16);
    cudaGetSymbolAddress((void**)&w1_16,  g_w1_16);
    cudaGetSymbolAddress((void**)&w2_16,  g_w2_16);
    cudaGetSymbolAddress((void**)&wlm16,  g_wlm16);

    cudaFuncSetAttribute(k_gemm_h<0,0,0,0>, cudaFuncAttributeMaxDynamicSharedMemorySize, GSMEM);
    cudaFuncSetAttribute(k_gemm_h<1,1,1,0>, cudaFuncAttributeMaxDynamicSharedMemorySize, GSMEM);
    cudaFuncSetAttribute(k_gemm_h<0,1,0,1>, cudaFuncAttributeMaxDynamicSharedMemorySize, GSMEM);
    cudaFuncSetAttribute(k_gemm_h<1,1,0,0>, cudaFuncAttributeMaxDynamicSharedMemorySize, GSMEM);

    // launch order chosen so ncu (-s 5 -c 1) lands on the proj GEMM:
    // [0] embed_ln  [1] repack  [2] cvtall  [3] qkv gemm  [4] attn  [5] proj gemm
    k_embed_ln<<<NTOK,96>>>(idx, tok, pos, ln1g, ln1b, x, xn16);
    k_repack<<<(NL*ND*NQKV + 255)/256, 256>>>(Wq, Wk, Wv, wqkv16);
    k_cvtall<<<(CVT_TOT + 255)/256, 256>>>(Wproj, W1, W2, Wlm,
        (u32*)wproj16, (u32*)w1_16, (u32*)w2_16, (u32*)wlm16);

    for (int l = 0; l < NL; l++){
        if (l > 0)
            k_ln<<<NTOK,96>>>(x, ln1g + l*ND, ln1b + l*ND, xn16);
        k_gemm_h<0,0,0,0><<<dim3(NQKV/128, NTOK/128),256,GSMEM>>>(
            xn16, wqkv16 + (size_t)l*ND*NQKV, (const float*)0, (float*)0, qkv16,
            NTOK, NQKV, ND);
        k_attn_h<<<dim3(NB*NH, 4),128>>>(qkv16, xn16);
        k_gemm_h<1,1,1,0><<<dim3(ND/128, NTOK/128),256,GSMEM>>>(
            xn16, wproj16 + (size_t)l*ND*ND, bproj + l*ND, x, (u16*)0,
            NTOK, ND, ND);
        k_ln<<<NTOK,96>>>(x, ln2g + l*ND, ln2b + l*ND, xn16);
        k_gemm_h<0,1,0,1><<<dim3(NFF/128, NTOK/128),256,GSMEM>>>(
            xn16, w1_16 + (size_t)l*ND*NFF, b1 + l*NFF, (float*)0, ff16,
            NTOK, NFF, ND);
        k_gemm_h<1,1,1,0><<<dim3(ND/128, NTOK/128),256,GSMEM>>>(
            ff16, w2_16 + (size_t)l*NFF*ND, b2 + l*ND, x, (u16*)0,
            NTOK, ND, NFF);
    }
    k_ln<<<NTOK,96>>>(x, lnfg, lnfb, xn16);
    k_gemm_h<1,1,0,0><<<dim3(NV/128, NTOK/128),256,GSMEM>>>(
        xn16, wlm16, blm, out, (u16*)0, NTOK, NV, ND);
}